// round 2
// baseline (speedup 1.0000x reference)
#include <cuda_runtime.h>

#define TT 2048
#define DD 64
#define HH 64
#define NG 256   // 4*H gates
#define BB_TOT 256

// 512 MB scratch: precomputed input projections xg[b][t][g] (bias included)
__device__ float g_xg[(size_t)BB_TOT * TT * NG];

// Packed fp32x2 FMA (sm_100+): d = a*b + c on two packed floats.
__device__ __forceinline__ unsigned long long ffma2(unsigned long long a,
                                                    unsigned long long b,
                                                    unsigned long long c) {
    unsigned long long d;
    asm("fma.rn.f32x2 %0, %1, %2, %3;" : "=l"(d) : "l"(a), "l"(b), "l"(c));
    return d;
}

__device__ __forceinline__ float red2(unsigned long long v) {
    float lo, hi;
    asm("mov.b64 {%0, %1}, %2;" : "=f"(lo), "=f"(hi) : "l"(v));
    return lo + hi;
}

// 64-element dot: w in registers (16 x ulonglong2), v in shared (broadcast LDS.128)
__device__ __forceinline__ float dot64(const ulonglong2* __restrict__ w,
                                       const ulonglong2* v) {
    unsigned long long a0 = 0ull, a1 = 0ull;
#pragma unroll
    for (int j = 0; j < 16; ++j) {
        ulonglong2 h2 = v[j];
        a0 = ffma2(w[j].x, h2.x, a0);
        a1 = ffma2(w[j].y, h2.y, a1);
    }
    return red2(a0) + red2(a1);
}

__device__ __forceinline__ float sigm(float v) {
    return __fdividef(1.f, 1.f + __expf(-v));
}
__device__ __forceinline__ float tanh_(float v) {
    return 1.f - __fdividef(2.f, 1.f + __expf(2.f * v));
}

// ---------------------------------------------------------------------------
// Kernel 1: xg[row][g] = bias[g] + W_ih[g] . x[row]   for all B*T rows
// ---------------------------------------------------------------------------
__global__ void __launch_bounds__(256, 2)
xg_gemm(const float* __restrict__ x, const float* __restrict__ w_ih,
        const float* __restrict__ b_ih, const float* __restrict__ b_hh,
        int nrows)
{
    __shared__ __align__(16) float xs[32][DD];   // 32-row x tile (8 KB)

    const int tid = threadIdx.x;      // gate index
    ulonglong2 w[16];
    {
        const ulonglong2* wp = (const ulonglong2*)(w_ih + tid * DD);
#pragma unroll
        for (int j = 0; j < 16; ++j) w[j] = wp[j];
    }
    const float bias = b_ih[tid] + b_hh[tid];

    const int ntiles = nrows / 32;
    for (int tile = blockIdx.x; tile < ntiles; tile += gridDim.x) {
        // stage 32 rows (512 float4, 2 per thread, coalesced)
        const float4* src = (const float4*)(x + (size_t)tile * 32 * DD);
#pragma unroll
        for (int i = 0; i < 2; ++i) {
            int s = tid * 2 + i;
            ((float4*)xs)[s] = src[s];
        }
        __syncthreads();

        float* dst = g_xg + (size_t)tile * 32 * NG + tid;
#pragma unroll 4
        for (int r = 0; r < 32; ++r) {
            float s = bias + dot64(w, (const ulonglong2*)xs[r]);
            dst[r * NG] = s;
        }
        __syncthreads();
    }
}

// ---------------------------------------------------------------------------
// Kernel 2: recurrence. 128 blocks x 256 threads, 2 batches per block.
// Thread g owns gate g (register-resident W_hh row); activations applied
// gate-locally in phase 1; phase 2 is the tiny elementwise cell update.
// ---------------------------------------------------------------------------
__global__ void __launch_bounds__(256, 1)
lstm_rec(const float* __restrict__ w_hh, const float* __restrict__ fc_w,
         const float* __restrict__ fc_b, float* __restrict__ out, int Tn)
{
    __shared__ __align__(16) float hsm[2][HH];
    __shared__ __align__(16) float gact[2][NG];   // activated gates

    const int tid = threadIdx.x;
    const int g = tid;
    const int b0 = blockIdx.x * 2;

    ulonglong2 whh[16];
    {
        const ulonglong2* wp = (const ulonglong2*)(w_hh + g * HH);
#pragma unroll
        for (int j = 0; j < 16; ++j) whh[j] = wp[j];
    }

    const float* xp0 = g_xg + (size_t)(b0 + 0) * Tn * NG + g;
    const float* xp1 = g_xg + (size_t)(b0 + 1) * Tn * NG + g;

    // register prefetch pipeline, distance 2
    float r0 = xp0[0],    r1 = xp1[0];
    float p0 = xp0[NG],   p1 = xp1[NG];
    xp0 += 2 * NG; xp1 += 2 * NG;

    if (tid < 128) ((float*)hsm)[tid] = 0.f;
    __syncthreads();

    const bool is_tanh_gate = ((g >> 6) == 2);   // warp-uniform (warps 4,5)
    float c = 0.f;

    for (int t = 0; t < Tn; ++t) {
        float s0 = r0 + dot64(whh, (const ulonglong2*)hsm[0]);
        float s1 = r1 + dot64(whh, (const ulonglong2*)hsm[1]);

        // rotate prefetch; issue next LDG early so it overlaps phase 2
        r0 = p0; r1 = p1;
        if (t < Tn - 2) {
            p0 = *xp0; p1 = *xp1;
            xp0 += NG; xp1 += NG;
        }

        float a0, a1;
        if (is_tanh_gate) { a0 = tanh_(s0); a1 = tanh_(s1); }
        else              { a0 = sigm(s0);  a1 = sigm(s1);  }
        gact[0][g] = a0;
        gact[1][g] = a1;
        __syncthreads();

        if (tid < 128) {
            int bb = tid >> 6, u = tid & 63;
            float gi = gact[bb][u];
            float gf = gact[bb][64 + u];
            float gg = gact[bb][128 + u];
            float go = gact[bb][192 + u];
            c = gf * c + gi * gg;
            hsm[bb][u] = go * tanh_(c);
        }
        __syncthreads();
    }

    // final FC: out[b, o] = h_last . fc_w[o] + fc_b[o]
    if (tid < 16) {
        int bb = tid >> 3, o = tid & 7;
        float s = fc_b[o];
#pragma unroll
        for (int k = 0; k < HH; ++k) s += hsm[bb][k] * fc_w[o * HH + k];
        out[(b0 + bb) * 8 + o] = s;
    }
}

extern "C" void kernel_launch(void* const* d_in, const int* in_sizes, int n_in,
                              void* d_out, int out_size) {
    const float* x    = (const float*)d_in[0];
    const float* w_ih = (const float*)d_in[1];
    const float* w_hh = (const float*)d_in[2];
    const float* b_ih = (const float*)d_in[3];
    const float* b_hh = (const float*)d_in[4];
    const float* fc_w = (const float*)d_in[5];
    const float* fc_b = (const float*)d_in[6];
    float* out = (float*)d_out;

    const int B = in_sizes[0] / (TT * DD);   // 256
    const int nrows = B * TT;

    xg_gemm<<<296, 256>>>(x, w_ih, b_ih, b_hh, nrows);
    lstm_rec<<<B / 2, 256>>>(w_hh, fc_w, fc_b, out, TT);
}